// round 1
// baseline (speedup 1.0000x reference)
#include <cuda_runtime.h>
#include <cuda_bf16.h>
#include <math_constants.h>

// Problem constants
#define EMBED 2048
#define NHEAD 16
#define NKV   4
#define HDIM  128
#define BB    2
#define SS    2048
#define MROWS (BB*SS)          // 4096
#define KVDIM (NKV*HDIM)       // 512

// -------- scratch (no allocation allowed) --------
__device__ float g_q  [MROWS * EMBED];   // [B*S, H*D]
__device__ float g_k  [MROWS * KVDIM];   // [B*S, Hkv*D]
__device__ float g_v  [MROWS * KVDIM];
__device__ float g_ctx[MROWS * EMBED];

// ============================================================
// SGEMM: C[M,N] = A[M,K] @ B[K,N], all row-major, fp32.
// BM=BN=128, BK=8, 256 threads, 8x8 microtile.
// Requires M%128==0, N%128==0, K%8==0 (true for all our shapes).
// ============================================================
__global__ __launch_bounds__(256, 2)
void sgemm128(int M, int N, int K,
              const float* __restrict__ A,
              const float* __restrict__ B,
              float* __restrict__ C)
{
    __shared__ float As[8][128];   // transposed: As[k][m]
    __shared__ float Bs[8][128];   // Bs[k][n]

    const int tid  = threadIdx.x;
    const int cRow = blockIdx.y;
    const int cCol = blockIdx.x;

    A += (size_t)cRow * 128 * K;
    B += (size_t)cCol * 128;
    C += (size_t)cRow * 128 * N + (size_t)cCol * 128;

    const int aRow = tid >> 1;            // 0..127
    const int aCol = (tid & 1) * 4;       // 0 or 4
    const int bRow = tid >> 5;            // 0..7
    const int bCol = (tid & 31) * 4;      // 0..124

    const int tr = (tid >> 4) * 8;        // row offset of microtile
    const int tc = (tid & 15) * 8;        // col offset of microtile

    float acc[8][8];
    #pragma unroll
    for (int i = 0; i < 8; i++)
        #pragma unroll
        for (int j = 0; j < 8; j++) acc[i][j] = 0.f;

    for (int k0 = 0; k0 < K; k0 += 8) {
        float4 a4 = *(const float4*)(A + (size_t)aRow * K + k0 + aCol);
        As[aCol + 0][aRow] = a4.x;
        As[aCol + 1][aRow] = a4.y;
        As[aCol + 2][aRow] = a4.z;
        As[aCol + 3][aRow] = a4.w;
        float4 b4 = *(const float4*)(B + (size_t)(k0 + bRow) * N + bCol);
        *(float4*)&Bs[bRow][bCol] = b4;
        __syncthreads();

        #pragma unroll
        for (int kk = 0; kk < 8; kk++) {
            float ra[8], rb[8];
            *(float4*)&ra[0] = *(const float4*)&As[kk][tr];
            *(float4*)&ra[4] = *(const float4*)&As[kk][tr + 4];
            *(float4*)&rb[0] = *(const float4*)&Bs[kk][tc];
            *(float4*)&rb[4] = *(const float4*)&Bs[kk][tc + 4];
            #pragma unroll
            for (int i = 0; i < 8; i++)
                #pragma unroll
                for (int j = 0; j < 8; j++)
                    acc[i][j] += ra[i] * rb[j];
        }
        __syncthreads();
    }

    #pragma unroll
    for (int i = 0; i < 8; i++) {
        #pragma unroll
        for (int j = 0; j < 8; j += 4) {
            float4 o;
            o.x = acc[i][j + 0]; o.y = acc[i][j + 1];
            o.z = acc[i][j + 2]; o.w = acc[i][j + 3];
            *(float4*)(C + (size_t)(tr + i) * N + tc + j) = o;
        }
    }
}

// ============================================================
// Fused flash attention (fp32, online softmax).
// grid: (S/64, NHEAD, BB), block: 256 threads (16x16).
// Each CTA: 64 q rows; iterates 64-row KV tiles.
// Thread (tx,ty): score microtile rows ty*4..+3 x cols tx*4..+3,
// O accumulator rows ty*4..+3 x d-slice tx*8..+7.
// smem: Qst[128][64], Kst[128][64], Vs[64][128], Ps[64][64], ms[64]
// ============================================================
#define ATTN_SMEM ((128*64 + 128*64 + 64*128 + 64*64 + 64) * sizeof(float))

__global__ __launch_bounds__(256, 1)
void attn_kernel(const float* __restrict__ Q,
                 const float* __restrict__ Kg,
                 const float* __restrict__ Vg,
                 const float* __restrict__ maskp,
                 float* __restrict__ O)
{
    extern __shared__ float sm[];
    float* Qst = sm;                   // [128][64]  Qst[d*64 + r]
    float* Kst = Qst + 128 * 64;       // [128][64]
    float* Vs  = Kst + 128 * 64;       // [64][128]  Vs[c*128 + d]
    float* Ps  = Vs  + 64 * 128;       // [64][64]
    float* ms  = Ps  + 64 * 64;        // [64]

    const int tid = threadIdx.x;
    const int tx  = tid & 15;
    const int ty  = tid >> 4;
    const int qt  = blockIdx.x;
    const int h   = blockIdx.y;
    const int b   = blockIdx.z;
    const int kh  = h >> 2;            // NHEAD/NKV = 4
    const int q0  = qt * 64;

    const float scale = 0.08838834764831845f;  // 1/sqrt(128)

    // load Q tile transposed
    for (int idx = tid; idx < 64 * 32; idx += 256) {
        int r  = idx >> 5;
        int d  = (idx & 31) * 4;
        float4 qv = *(const float4*)(Q + ((size_t)(b * SS + q0 + r) * NHEAD + h) * HDIM + d);
        Qst[(d + 0) * 64 + r] = qv.x;
        Qst[(d + 1) * 64 + r] = qv.y;
        Qst[(d + 2) * 64 + r] = qv.z;
        Qst[(d + 3) * 64 + r] = qv.w;
    }

    float m[4], l[4], o[4][8];
    #pragma unroll
    for (int i = 0; i < 4; i++) {
        m[i] = -1e30f; l[i] = 0.f;
        #pragma unroll
        for (int d = 0; d < 8; d++) o[i][d] = 0.f;
    }
    __syncthreads();  // Qst ready (also covers first K/V load ordering)

    for (int kt = 0; kt < SS / 64; kt++) {
        const int kv0 = kt * 64;
        // load K (transposed) + V (direct) tiles
        for (int idx = tid; idx < 64 * 32; idx += 256) {
            int r = idx >> 5;
            int d = (idx & 31) * 4;
            size_t base = ((size_t)(b * SS + kv0 + r) * NKV + kh) * HDIM + d;
            float4 kv = *(const float4*)(Kg + base);
            Kst[(d + 0) * 64 + r] = kv.x;
            Kst[(d + 1) * 64 + r] = kv.y;
            Kst[(d + 2) * 64 + r] = kv.z;
            Kst[(d + 3) * 64 + r] = kv.w;
            float4 vv = *(const float4*)(Vg + base);
            *(float4*)(Vs + r * 128 + d) = vv;
        }
        if (tid < 64) ms[tid] = maskp[(size_t)b * SS + kv0 + tid];
        __syncthreads();

        // scores S = Q K^T  (4x4 per thread)
        float s[4][4];
        #pragma unroll
        for (int i = 0; i < 4; i++)
            #pragma unroll
            for (int j = 0; j < 4; j++) s[i][j] = 0.f;

        #pragma unroll 8
        for (int d = 0; d < 128; d++) {
            float4 qv = *(const float4*)(Qst + d * 64 + ty * 4);
            float4 kv = *(const float4*)(Kst + d * 64 + tx * 4);
            s[0][0] += qv.x * kv.x; s[0][1] += qv.x * kv.y; s[0][2] += qv.x * kv.z; s[0][3] += qv.x * kv.w;
            s[1][0] += qv.y * kv.x; s[1][1] += qv.y * kv.y; s[1][2] += qv.y * kv.z; s[1][3] += qv.y * kv.w;
            s[2][0] += qv.z * kv.x; s[2][1] += qv.z * kv.y; s[2][2] += qv.z * kv.z; s[2][3] += qv.z * kv.w;
            s[3][0] += qv.w * kv.x; s[3][1] += qv.w * kv.y; s[3][2] += qv.w * kv.z; s[3][3] += qv.w * kv.w;
        }

        // scale + mask
        #pragma unroll
        for (int j = 0; j < 4; j++) {
            float mb = (1.0f - ms[tx * 4 + j]) * -1e9f;
            #pragma unroll
            for (int i = 0; i < 4; i++) s[i][j] = s[i][j] * scale + mb;
        }

        // online softmax per row (row owned by 16 lanes = half warp)
        #pragma unroll
        for (int i = 0; i < 4; i++) {
            float mloc = fmaxf(fmaxf(s[i][0], s[i][1]), fmaxf(s[i][2], s[i][3]));
            #pragma unroll
            for (int off = 1; off < 16; off <<= 1)
                mloc = fmaxf(mloc, __shfl_xor_sync(0xffffffffu, mloc, off, 16));
            float mnew  = fmaxf(m[i], mloc);
            float alpha = __expf(m[i] - mnew);
            float p[4], psum = 0.f;
            #pragma unroll
            for (int j = 0; j < 4; j++) { p[j] = __expf(s[i][j] - mnew); psum += p[j]; }
            #pragma unroll
            for (int off = 1; off < 16; off <<= 1)
                psum += __shfl_xor_sync(0xffffffffu, psum, off, 16);
            l[i] = l[i] * alpha + psum;
            m[i] = mnew;
            #pragma unroll
            for (int d = 0; d < 8; d++) o[i][d] *= alpha;
            #pragma unroll
            for (int j = 0; j < 4; j++) Ps[(ty * 4 + i) * 64 + tx * 4 + j] = p[j];
        }
        __syncthreads();  // Ps visible

        // O += P @ V   (rows ty*4.., d-slice tx*8..)
        #pragma unroll 4
        for (int c = 0; c < 64; c++) {
            float4 v0 = *(const float4*)(Vs + c * 128 + tx * 8);
            float4 v1 = *(const float4*)(Vs + c * 128 + tx * 8 + 4);
            float p0 = Ps[(ty * 4 + 0) * 64 + c];
            float p1 = Ps[(ty * 4 + 1) * 64 + c];
            float p2 = Ps[(ty * 4 + 2) * 64 + c];
            float p3 = Ps[(ty * 4 + 3) * 64 + c];
            o[0][0] += p0 * v0.x; o[0][1] += p0 * v0.y; o[0][2] += p0 * v0.z; o[0][3] += p0 * v0.w;
            o[0][4] += p0 * v1.x; o[0][5] += p0 * v1.y; o[0][6] += p0 * v1.z; o[0][7] += p0 * v1.w;
            o[1][0] += p1 * v0.x; o[1][1] += p1 * v0.y; o[1][2] += p1 * v0.z; o[1][3] += p1 * v0.w;
            o[1][4] += p1 * v1.x; o[1][5] += p1 * v1.y; o[1][6] += p1 * v1.z; o[1][7] += p1 * v1.w;
            o[2][0] += p2 * v0.x; o[2][1] += p2 * v0.y; o[2][2] += p2 * v0.z; o[2][3] += p2 * v0.w;
            o[2][4] += p2 * v1.x; o[2][5] += p2 * v1.y; o[2][6] += p2 * v1.z; o[2][7] += p2 * v1.w;
            o[3][0] += p3 * v0.x; o[3][1] += p3 * v0.y; o[3][2] += p3 * v0.z; o[3][3] += p3 * v0.w;
            o[3][4] += p3 * v1.x; o[3][5] += p3 * v1.y; o[3][6] += p3 * v1.z; o[3][7] += p3 * v1.w;
        }
        __syncthreads();  // done with Kst/Vs/Ps for this tile
    }

    // epilogue: normalize and write ctx [B,S,H,D]
    #pragma unroll
    for (int i = 0; i < 4; i++) {
        float inv = 1.0f / l[i];
        float4 w0, w1;
        w0.x = o[i][0] * inv; w0.y = o[i][1] * inv; w0.z = o[i][2] * inv; w0.w = o[i][3] * inv;
        w1.x = o[i][4] * inv; w1.y = o[i][5] * inv; w1.z = o[i][6] * inv; w1.w = o[i][7] * inv;
        size_t base = ((size_t)(b * SS + q0 + ty * 4 + i) * NHEAD + h) * HDIM + tx * 8;
        *(float4*)(O + base)     = w0;
        *(float4*)(O + base + 4) = w1;
    }
}

// ============================================================
// launcher
// ============================================================
extern "C" void kernel_launch(void* const* d_in, const int* in_sizes, int n_in,
                              void* d_out, int out_size)
{
    const float* query = (const float*)d_in[0];
    const float* key   = (const float*)d_in[1];
    const float* value = (const float*)d_in[2];
    const float* mask  = (const float*)d_in[3];
    const float* Wq    = (const float*)d_in[4];
    const float* Wk    = (const float*)d_in[5];
    const float* Wv    = (const float*)d_in[6];
    const float* Wo    = (const float*)d_in[7];
    float* out = (float*)d_out;

    float *q, *k, *v, *ctx;
    cudaGetSymbolAddress((void**)&q,   g_q);
    cudaGetSymbolAddress((void**)&k,   g_k);
    cudaGetSymbolAddress((void**)&v,   g_v);
    cudaGetSymbolAddress((void**)&ctx, g_ctx);

    cudaFuncSetAttribute(attn_kernel, cudaFuncAttributeMaxDynamicSharedMemorySize,
                         (int)ATTN_SMEM);

    dim3 blk(256);
    // projections
    sgemm128<<<dim3(EMBED / 128, MROWS / 128), blk>>>(MROWS, EMBED, EMBED, query, Wq, q);
    sgemm128<<<dim3(KVDIM / 128, MROWS / 128), blk>>>(MROWS, KVDIM, EMBED, key,   Wk, k);
    sgemm128<<<dim3(KVDIM / 128, MROWS / 128), blk>>>(MROWS, KVDIM, EMBED, value, Wv, v);
    // fused attention
    attn_kernel<<<dim3(SS / 64, NHEAD, BB), blk, ATTN_SMEM>>>(q, k, v, mask, ctx);
    // output projection -> d_out
    sgemm128<<<dim3(EMBED / 128, MROWS / 128), blk>>>(MROWS, EMBED, EMBED, ctx, Wo, out);
}

// round 3
// speedup vs baseline: 3.6645x; 3.6645x over previous
#include <cuda_runtime.h>
#include <cuda_bf16.h>
#include <cstdint>

// Problem constants
#define EMBED 2048
#define NHEAD 16
#define NKV   4
#define HDIM  128
#define BB    2
#define SS    2048
#define MROWS (BB*SS)          // 4096
#define KVDIM (NKV*HDIM)       // 512

// -------- scratch (no allocation allowed) --------
__device__ __nv_bfloat16 g_qh[MROWS * EMBED];
__device__ __nv_bfloat16 g_ql[MROWS * EMBED];
__device__ __nv_bfloat16 g_kh[MROWS * KVDIM];
__device__ __nv_bfloat16 g_kl[MROWS * KVDIM];
__device__ __nv_bfloat16 g_vh[MROWS * KVDIM];
__device__ __nv_bfloat16 g_vl[MROWS * KVDIM];
__device__ float         g_ctx[MROWS * EMBED];

// ======================= helpers =======================
__device__ __forceinline__ uint32_t sptr(const void* p) {
    return (uint32_t)__cvta_generic_to_shared(p);
}

__device__ __forceinline__ void ldsm4(uint32_t& r0, uint32_t& r1, uint32_t& r2, uint32_t& r3, uint32_t a) {
    asm volatile("ldmatrix.sync.aligned.m8n8.x4.shared.b16 {%0,%1,%2,%3},[%4];"
                 : "=r"(r0), "=r"(r1), "=r"(r2), "=r"(r3) : "r"(a));
}
__device__ __forceinline__ void ldsm4t(uint32_t& r0, uint32_t& r1, uint32_t& r2, uint32_t& r3, uint32_t a) {
    asm volatile("ldmatrix.sync.aligned.m8n8.x4.trans.shared.b16 {%0,%1,%2,%3},[%4];"
                 : "=r"(r0), "=r"(r1), "=r"(r2), "=r"(r3) : "r"(a));
}
__device__ __forceinline__ void mma_bf16(float* c, const uint32_t* a, uint32_t b0, uint32_t b1) {
    asm volatile(
        "mma.sync.aligned.m16n8k16.row.col.f32.bf16.bf16.f32 "
        "{%0,%1,%2,%3},{%4,%5,%6,%7},{%8,%9},{%0,%1,%2,%3};"
        : "+f"(c[0]), "+f"(c[1]), "+f"(c[2]), "+f"(c[3])
        : "r"(a[0]), "r"(a[1]), "r"(a[2]), "r"(a[3]), "r"(b0), "r"(b1));
}
// pack two floats to bf16x2 (lo = first arg)
__device__ __forceinline__ uint32_t packbf2(float lo, float hi) {
    uint32_t r;
    asm("cvt.rn.bf16x2.f32 %0, %1, %2;" : "=r"(r) : "f"(hi), "f"(lo));
    return r;
}

__device__ __forceinline__ void split_store4(float4 v, __nv_bfloat16* ph, __nv_bfloat16* pl) {
    __nv_bfloat16 h0 = __float2bfloat16_rn(v.x), h1 = __float2bfloat16_rn(v.y),
                  h2 = __float2bfloat16_rn(v.z), h3 = __float2bfloat16_rn(v.w);
    ((__nv_bfloat162*)ph)[0] = __halves2bfloat162(h0, h1);
    ((__nv_bfloat162*)ph)[1] = __halves2bfloat162(h2, h3);
    ((__nv_bfloat162*)pl)[0] = __floats2bfloat162_rn(v.x - __bfloat162float(h0), v.y - __bfloat162float(h1));
    ((__nv_bfloat162*)pl)[1] = __floats2bfloat162_rn(v.z - __bfloat162float(h2), v.w - __bfloat162float(h3));
}
__device__ __forceinline__ void split_store2(float v0, float v1, __nv_bfloat16* ph, __nv_bfloat16* pl) {
    __nv_bfloat16 h0 = __float2bfloat16_rn(v0), h1 = __float2bfloat16_rn(v1);
    *(__nv_bfloat162*)ph = __halves2bfloat162(h0, h1);
    *(__nv_bfloat162*)pl = __floats2bfloat162_rn(v0 - __bfloat162float(h0), v1 - __bfloat162float(h1));
}

// ============================================================
// GEMM C = A@B (fp32 in), computed as 3-term bf16 split MMA.
// BM=BN=128, BK=32, 256 threads (8 warps, 2x4), warp tile 64x32.
// SPLIT_OUT: write C as bf16 hi/lo pair; else fp32.
// ============================================================
#define ALD 40    // 32 + 8 pad (bf16 elems)
#define BLD 136   // 128 + 8 pad
#define GEMM_SMEM ((128*ALD*2 + 32*BLD*2) * 2)  // bytes

template<bool SPLIT_OUT>
__global__ __launch_bounds__(256, 1)
void gemm_bf16x3(int M, int N, int K,
                 const float* __restrict__ A,
                 const float* __restrict__ B,
                 float* __restrict__ Cf,
                 __nv_bfloat16* __restrict__ Ch,
                 __nv_bfloat16* __restrict__ Cl)
{
    extern __shared__ char sm8[];
    __nv_bfloat16* Ah = (__nv_bfloat16*)sm8;            // [128][40]
    __nv_bfloat16* Al = Ah + 128 * ALD;
    __nv_bfloat16* Bh = Al + 128 * ALD;                 // [32][136]
    __nv_bfloat16* Bl = Bh + 32 * BLD;

    const int tid = threadIdx.x;
    const int bm = blockIdx.y, bn = blockIdx.x;
    const float* Aptr = A + (size_t)bm * 128 * K;
    const float* Bptr = B + (size_t)bn * 128;

    float4 ra[4], rb[4];
    #pragma unroll
    for (int i = 0; i < 4; i++) {
        int id = tid + 256 * i;
        ra[i] = *(const float4*)(Aptr + (size_t)(id >> 3) * K + (id & 7) * 4);
        rb[i] = *(const float4*)(Bptr + (size_t)(id >> 5) * N + (id & 31) * 4);
    }

    float acc[4][4][4];
    #pragma unroll
    for (int mt = 0; mt < 4; mt++)
        #pragma unroll
        for (int nt = 0; nt < 4; nt++)
            #pragma unroll
            for (int i = 0; i < 4; i++) acc[mt][nt][i] = 0.f;

    const int w = tid >> 5, lane = tid & 31;
    const int m0w = (w >> 2) * 64, n0w = (w & 3) * 32;
    const int arow = lane & 15, asel = (lane >> 4) * 8;
    const int brow = (lane & 7) + (lane & 8);
    const int bsel = (lane & 16) >> 1;

    for (int k0 = 0; k0 < K; k0 += 32) {
        __syncthreads();
        #pragma unroll
        for (int i = 0; i < 4; i++) {
            int id = tid + 256 * i;
            split_store4(ra[i], &Ah[(id >> 3) * ALD + (id & 7) * 4], &Al[(id >> 3) * ALD + (id & 7) * 4]);
            split_store4(rb[i], &Bh[(id >> 5) * BLD + (id & 31) * 4], &Bl[(id >> 5) * BLD + (id & 31) * 4]);
        }
        __syncthreads();
        if (k0 + 32 < K) {
            #pragma unroll
            for (int i = 0; i < 4; i++) {
                int id = tid + 256 * i;
                ra[i] = *(const float4*)(Aptr + (size_t)(id >> 3) * K + k0 + 32 + (id & 7) * 4);
                rb[i] = *(const float4*)(Bptr + (size_t)(k0 + 32 + (id >> 5)) * N + (id & 31) * 4);
            }
        }
        #pragma unroll
        for (int kk = 0; kk < 2; kk++) {
            uint32_t ah[4][4], al[4][4];
            #pragma unroll
            for (int mt = 0; mt < 4; mt++) {
                int off = (m0w + 16 * mt + arow) * ALD + 16 * kk + asel;
                ldsm4(ah[mt][0], ah[mt][1], ah[mt][2], ah[mt][3], sptr(&Ah[off]));
                ldsm4(al[mt][0], al[mt][1], al[mt][2], al[mt][3], sptr(&Al[off]));
            }
            uint32_t bh[4][2], bl[4][2];
            #pragma unroll
            for (int nt2 = 0; nt2 < 2; nt2++) {
                int off = (16 * kk + brow) * BLD + n0w + 16 * nt2 + bsel;
                uint32_t r0, r1, r2, r3;
                ldsm4t(r0, r1, r2, r3, sptr(&Bh[off]));
                bh[2*nt2][0] = r0; bh[2*nt2][1] = r1; bh[2*nt2+1][0] = r2; bh[2*nt2+1][1] = r3;
                ldsm4t(r0, r1, r2, r3, sptr(&Bl[off]));
                bl[2*nt2][0] = r0; bl[2*nt2][1] = r1; bl[2*nt2+1][0] = r2; bl[2*nt2+1][1] = r3;
            }
            #pragma unroll
            for (int mt = 0; mt < 4; mt++)
                #pragma unroll
                for (int nt = 0; nt < 4; nt++) {
                    mma_bf16(acc[mt][nt], ah[mt], bh[nt][0], bh[nt][1]);
                    mma_bf16(acc[mt][nt], ah[mt], bl[nt][0], bl[nt][1]);
                    mma_bf16(acc[mt][nt], al[mt], bh[nt][0], bh[nt][1]);
                }
        }
    }

    // epilogue
    const int g = lane >> 2, t = lane & 3;
    #pragma unroll
    for (int mt = 0; mt < 4; mt++)
        #pragma unroll
        for (int nt = 0; nt < 4; nt++) {
            size_t r0 = (size_t)bm * 128 + m0w + 16 * mt + g;
            size_t c0 = (size_t)bn * 128 + n0w + 8 * nt + 2 * t;
            if (SPLIT_OUT) {
                split_store2(acc[mt][nt][0], acc[mt][nt][1], &Ch[r0 * N + c0], &Cl[r0 * N + c0]);
                split_store2(acc[mt][nt][2], acc[mt][nt][3], &Ch[(r0 + 8) * N + c0], &Cl[(r0 + 8) * N + c0]);
            } else {
                float2 u; u.x = acc[mt][nt][0]; u.y = acc[mt][nt][1];
                *(float2*)&Cf[r0 * N + c0] = u;
                float2 v; v.x = acc[mt][nt][2]; v.y = acc[mt][nt][3];
                *(float2*)&Cf[(r0 + 8) * N + c0] = v;
            }
        }
}

// ============================================================
// Flash attention, bf16-split MMA.
// grid (SS/128, NHEAD, BB), 256 threads (8 warps). Warp w owns
// q rows 16w..16w+15 of the CTA's 128. KV tile = 64.
// ============================================================
#define KLD 136
#define ATTN_SMEM (4 * 64 * KLD * 2 + 64 * 4)

__global__ __launch_bounds__(256, 1)
void attn_mma(const __nv_bfloat16* __restrict__ Qh, const __nv_bfloat16* __restrict__ Ql,
              const __nv_bfloat16* __restrict__ Kh, const __nv_bfloat16* __restrict__ Kl,
              const __nv_bfloat16* __restrict__ Vh, const __nv_bfloat16* __restrict__ Vl,
              const float* __restrict__ maskp, float* __restrict__ ctx)
{
    extern __shared__ char sm8[];
    __nv_bfloat16* sKh = (__nv_bfloat16*)sm8;      // [64][136]
    __nv_bfloat16* sKl = sKh + 64 * KLD;
    __nv_bfloat16* sVh = sKl + 64 * KLD;
    __nv_bfloat16* sVl = sVh + 64 * KLD;
    float* mb = (float*)(sVl + 64 * KLD);          // [64]

    const int tid = threadIdx.x;
    const int w = tid >> 5, lane = tid & 31;
    const int g = lane >> 2, t = lane & 3;
    const int h = blockIdx.y, b = blockIdx.z, kh = h >> 2;
    const size_t qrow0 = (size_t)b * SS + blockIdx.x * 128 + w * 16;

    const float scale = 0.08838834764831845f;  // 1/sqrt(128)

    // preload Q fragments (kept for all 32 KV tiles)
    uint32_t qfh[8][4], qfl[8][4];
    {
        const __nv_bfloat16* qh0 = Qh + qrow0 * EMBED + h * HDIM;
        const __nv_bfloat16* ql0 = Ql + qrow0 * EMBED + h * HDIM;
        #pragma unroll
        for (int kk = 0; kk < 8; kk++) {
            int c0 = 16 * kk + 2 * t;
            qfh[kk][0] = *(const uint32_t*)(qh0 + (size_t)g * EMBED + c0);
            qfh[kk][1] = *(const uint32_t*)(qh0 + (size_t)(g + 8) * EMBED + c0);
            qfh[kk][2] = *(const uint32_t*)(qh0 + (size_t)g * EMBED + c0 + 8);
            qfh[kk][3] = *(const uint32_t*)(qh0 + (size_t)(g + 8) * EMBED + c0 + 8);
            qfl[kk][0] = *(const uint32_t*)(ql0 + (size_t)g * EMBED + c0);
            qfl[kk][1] = *(const uint32_t*)(ql0 + (size_t)(g + 8) * EMBED + c0);
            qfl[kk][2] = *(const uint32_t*)(ql0 + (size_t)g * EMBED + c0 + 8);
            qfl[kk][3] = *(const uint32_t*)(ql0 + (size_t)(g + 8) * EMBED + c0 + 8);
        }
    }

    float o[16][4];
    #pragma unroll
    for (int nt = 0; nt < 16; nt++)
        #pragma unroll
        for (int i = 0; i < 4; i++) o[nt][i] = 0.f;
    float m0 = -1e30f, m1 = -1e30f, l0 = 0.f, l1 = 0.f;

    const int vrow = (lane & 7) + (lane & 8);
    const int vsel = (lane & 16) >> 1;

    for (int kt = 0; kt < SS / 64; kt++) {
        const int kv0 = kt * 64;
        __syncthreads();
        {
            const size_t gbase = ((size_t)b * SS + kv0) * KVDIM + kh * HDIM;
            #pragma unroll
            for (int i = 0; i < 4; i++) {
                int id = tid + 256 * i;
                int r = id >> 4, c8 = (id & 15) * 8;
                size_t go = gbase + (size_t)r * KVDIM + c8;
                int so = r * KLD + c8;
                *(uint4*)&sKh[so] = *(const uint4*)(Kh + go);
                *(uint4*)&sKl[so] = *(const uint4*)(Kl + go);
                *(uint4*)&sVh[so] = *(const uint4*)(Vh + go);
                *(uint4*)&sVl[so] = *(const uint4*)(Vl + go);
            }
            if (tid < 64) mb[tid] = (1.0f - maskp[(size_t)b * SS + kv0 + tid]) * -1e9f;
        }
        __syncthreads();

        // ---- S = Q K^T ----
        float s[8][4];
        #pragma unroll
        for (int nt = 0; nt < 8; nt++)
            #pragma unroll
            for (int i = 0; i < 4; i++) s[nt][i] = 0.f;

        #pragma unroll
        for (int kk = 0; kk < 8; kk++) {
            #pragma unroll
            for (int nt2 = 0; nt2 < 4; nt2++) {
                int row = 16 * nt2 + (lane & 15);
                int col = 16 * kk + (lane >> 4) * 8;
                uint32_t r0, r1, r2, r3, u0, u1, u2, u3;
                ldsm4(r0, r1, r2, r3, sptr(&sKh[row * KLD + col]));
                ldsm4(u0, u1, u2, u3, sptr(&sKl[row * KLD + col]));
                mma_bf16(s[2*nt2],   qfh[kk], r0, r2);
                mma_bf16(s[2*nt2+1], qfh[kk], r1, r3);
                mma_bf16(s[2*nt2],   qfh[kk], u0, u2);
                mma_bf16(s[2*nt2+1], qfh[kk], u1, u3);
                mma_bf16(s[2*nt2],   qfl[kk], r0, r2);
                mma_bf16(s[2*nt2+1], qfl[kk], r1, r3);
            }
        }

        // ---- scale + mask + online softmax ----
        float rm0 = -1e30f, rm1 = -1e30f;
        #pragma unroll
        for (int nt = 0; nt < 8; nt++) {
            float cb0 = mb[8 * nt + 2 * t];
            float cb1 = mb[8 * nt + 2 * t + 1];
            s[nt][0] = s[nt][0] * scale + cb0;
            s[nt][1] = s[nt][1] * scale + cb1;
            s[nt][2] = s[nt][2] * scale + cb0;
            s[nt][3] = s[nt][3] * scale + cb1;
            rm0 = fmaxf(rm0, fmaxf(s[nt][0], s[nt][1]));
            rm1 = fmaxf(rm1, fmaxf(s[nt][2], s[nt][3]));
        }
        rm0 = fmaxf(rm0, __shfl_xor_sync(0xffffffffu, rm0, 1));
        rm0 = fmaxf(rm0, __shfl_xor_sync(0xffffffffu, rm0, 2));
        rm1 = fmaxf(rm1, __shfl_xor_sync(0xffffffffu, rm1, 1));
        rm1 = fmaxf(rm1, __shfl_xor_sync(0xffffffffu, rm1, 2));
        float mn0 = fmaxf(m0, rm0), mn1 = fmaxf(m1, rm1);
        float a0 = __expf(m0 - mn0), a1 = __expf(m1 - mn1);
        m0 = mn0; m1 = mn1;

        float ps0 = 0.f, ps1 = 0.f;
        #pragma unroll
        for (int nt = 0; nt < 8; nt++) {
            s[nt][0] = __expf(s[nt][0] - mn0);
            s[nt][1] = __expf(s[nt][1] - mn0);
            s[nt][2] = __expf(s[nt][2] - mn1);
            s[nt][3] = __expf(s[nt][3] - mn1);
            ps0 += s[nt][0] + s[nt][1];
            ps1 += s[nt][2] + s[nt][3];
        }
        ps0 += __shfl_xor_sync(0xffffffffu, ps0, 1);
        ps0 += __shfl_xor_sync(0xffffffffu, ps0, 2);
        ps1 += __shfl_xor_sync(0xffffffffu, ps1, 1);
        ps1 += __shfl_xor_sync(0xffffffffu, ps1, 2);
        l0 = l0 * a0 + ps0;
        l1 = l1 * a1 + ps1;

        #pragma unroll
        for (int nt = 0; nt < 16; nt++) {
            o[nt][0] *= a0; o[nt][1] *= a0;
            o[nt][2] *= a1; o[nt][3] *= a1;
        }

        // ---- pack P fragments (hi/lo split, in-register remap) ----
        // C-frag of score tile pair (2j, 2j+1) becomes the A-frag for the
        // k-block j of the PV mma: a = [c01(2j), c23(2j), c01(2j+1), c23(2j+1)]
        uint32_t pah[4][4], pal[4][4];
        #pragma unroll
        for (int j = 0; j < 4; j++) {
            #pragma unroll
            for (int half = 0; half < 2; half++) {
                float v0 = s[2*j + half][0], v1 = s[2*j + half][1];
                float v2 = s[2*j + half][2], v3 = s[2*j + half][3];
                float h0 = __bfloat162float(__float2bfloat16_rn(v0));
                float h1 = __bfloat162float(__float2bfloat16_rn(v1));
                float h2 = __bfloat162float(__float2bfloat16_rn(v2));
                float h3 = __bfloat162float(__float2bfloat16_rn(v3));
                pah[j][2*half + 0] = packbf2(h0, h1);
                pah[j][2*half + 1] = packbf2(h2, h3);
                pal[j][2*half + 0] = packbf2(v0 - h0, v1 - h1);
                pal[j][2*half + 1] = packbf2(v2 - h2, v3 - h3);
            }
        }

        // ---- O += P V ----
        #pragma unroll
        for (int j = 0; j < 4; j++) {
            #pragma unroll
            for (int nt2 = 0; nt2 < 8; nt2++) {
                int row = 16 * j + vrow;
                int col = 16 * nt2 + vsel;
                uint32_t r0, r1, r2, r3, u0, u1, u2, u3;
                ldsm4t(r0, r1, r2, r3, sptr(&sVh[row * KLD + col]));
                ldsm4t(u0, u1, u2, u3, sptr(&sVl[row * KLD + col]));
                mma_bf16(o[2*nt2],   pah[j], r0, r1);
                mma_bf16(o[2*nt2+1], pah[j], r2, r3);
                mma_bf16(o[2*nt2],   pah[j], u0, u1);
                mma_bf16(o[2*nt2+1], pah[j], u2, u3);
                mma_bf16(o[2*nt2],   pal[j], r0, r1);
                mma_bf16(o[2*nt2+1], pal[j], r2, r3);
            }
        }
    }

    // ---- epilogue ----
    float i0 = 1.0f / l0, i1 = 1.0f / l1;
    float* c0p = ctx + (qrow0 + g) * EMBED + h * HDIM + 2 * t;
    float* c1p = ctx + (qrow0 + g + 8) * EMBED + h * HDIM + 2 * t;
    #pragma unroll
    for (int nt = 0; nt < 16; nt++) {
        float2 u; u.x = o[nt][0] * i0; u.y = o[nt][1] * i0;
        *(float2*)(c0p + 8 * nt) = u;
        float2 v; v.x = o[nt][2] * i1; v.y = o[nt][3] * i1;
        *(float2*)(c1p + 8 * nt) = v;
    }
}

// ============================================================
// launcher
// ============================================================
extern "C" void kernel_launch(void* const* d_in, const int* in_sizes, int n_in,
                              void* d_out, int out_size)
{
    const float* query = (const float*)d_in[0];
    const float* key   = (const float*)d_in[1];
    const float* value = (const float*)d_in[2];
    const float* mask  = (const float*)d_in[3];
    const float* Wq    = (const float*)d_in[4];
    const float* Wk    = (const float*)d_in[5];
    const float* Wv    = (const float*)d_in[6];
    const float* Wo    = (const float*)d_in[7];
    float* out = (float*)d_out;

    __nv_bfloat16 *qh, *ql, *kh, *kl, *vh, *vl;
    float* ctx;
    cudaGetSymbolAddress((void**)&qh, g_qh);
    cudaGetSymbolAddress((void**)&ql, g_ql);
    cudaGetSymbolAddress((void**)&kh, g_kh);
    cudaGetSymbolAddress((void**)&kl, g_kl);
    cudaGetSymbolAddress((void**)&vh, g_vh);
    cudaGetSymbolAddress((void**)&vl, g_vl);
    cudaGetSymbolAddress((void**)&ctx, g_ctx);

    static int inited = 0;
    if (!inited) {
        cudaFuncSetAttribute(attn_mma, cudaFuncAttributeMaxDynamicSharedMemorySize, ATTN_SMEM);
        cudaFuncSetAttribute(gemm_bf16x3<true>,  cudaFuncAttributeMaxDynamicSharedMemorySize, GEMM_SMEM);
        cudaFuncSetAttribute(gemm_bf16x3<false>, cudaFuncAttributeMaxDynamicSharedMemorySize, GEMM_SMEM);
        inited = 1;
    }

    dim3 blk(256);
    // projections (write split bf16)
    gemm_bf16x3<true><<<dim3(EMBED / 128, MROWS / 128), blk, GEMM_SMEM>>>(
        MROWS, EMBED, EMBED, query, Wq, nullptr, qh, ql);
    gemm_bf16x3<true><<<dim3(KVDIM / 128, MROWS / 128), blk, GEMM_SMEM>>>(
        MROWS, KVDIM, EMBED, key, Wk, nullptr, kh, kl);
    gemm_bf16x3<true><<<dim3(KVDIM / 128, MROWS / 128), blk, GEMM_SMEM>>>(
        MROWS, KVDIM, EMBED, value, Wv, nullptr, vh, vl);
    // fused attention
    attn_mma<<<dim3(SS / 128, NHEAD, BB), blk, ATTN_SMEM>>>(qh, ql, kh, kl, vh, vl, mask, ctx);
    // output projection (fp32 out)
    gemm_bf16x3<false><<<dim3(EMBED / 128, MROWS / 128), blk, GEMM_SMEM>>>(
        MROWS, EMBED, EMBED, ctx, Wo, out, nullptr, nullptr);
}

// round 4
// speedup vs baseline: 3.6866x; 1.0060x over previous
#include <cuda_runtime.h>
#include <cuda_bf16.h>
#include <cstdint>

// Problem constants
#define EMBED 2048
#define NHEAD 16
#define NKV   4
#define HDIM  128
#define BB    2
#define SS    2048
#define MROWS (BB*SS)          // 4096
#define KVDIM (NKV*HDIM)       // 512

typedef __nv_bfloat16 bf16;

// -------- scratch (no allocation allowed) --------
// pre-split inputs (query,key,value) and weights
#define IN_STRIDE (MROWS * EMBED)                 // 8388608
__device__ bf16 g_inh[3 * IN_STRIDE];
__device__ bf16 g_inl[3 * IN_STRIDE];
#define WQ_OFF 0
#define WK_OFF (EMBED*EMBED)                      // 4194304
#define WV_OFF (WK_OFF + EMBED*KVDIM)             // 5242880
#define WO_OFF (WV_OFF + EMBED*KVDIM)             // 6291456
#define W_TOTAL (WO_OFF + EMBED*EMBED)            // 10485760
__device__ bf16 g_wh[W_TOTAL];
__device__ bf16 g_wl[W_TOTAL];
// projected q/k/v (split) and attention context (split)
__device__ bf16 g_qh[MROWS * EMBED];
__device__ bf16 g_ql[MROWS * EMBED];
__device__ bf16 g_kh[MROWS * KVDIM];
__device__ bf16 g_kl[MROWS * KVDIM];
__device__ bf16 g_vh[MROWS * KVDIM];
__device__ bf16 g_vl[MROWS * KVDIM];
__device__ bf16 g_ctxh[MROWS * EMBED];
__device__ bf16 g_ctxl[MROWS * EMBED];

// ======================= helpers =======================
__device__ __forceinline__ uint32_t sptr(const void* p) {
    return (uint32_t)__cvta_generic_to_shared(p);
}
__device__ __forceinline__ void cpa16(uint32_t dst, const void* src) {
    asm volatile("cp.async.cg.shared.global [%0], [%1], 16;" :: "r"(dst), "l"(src));
}
#define CP_COMMIT() asm volatile("cp.async.commit_group;")
#define CP_WAIT(n)  asm volatile("cp.async.wait_group %0;" :: "n"(n))

__device__ __forceinline__ void ldsm4(uint32_t& r0, uint32_t& r1, uint32_t& r2, uint32_t& r3, uint32_t a) {
    asm volatile("ldmatrix.sync.aligned.m8n8.x4.shared.b16 {%0,%1,%2,%3},[%4];"
                 : "=r"(r0), "=r"(r1), "=r"(r2), "=r"(r3) : "r"(a));
}
__device__ __forceinline__ void ldsm4t(uint32_t& r0, uint32_t& r1, uint32_t& r2, uint32_t& r3, uint32_t a) {
    asm volatile("ldmatrix.sync.aligned.m8n8.x4.trans.shared.b16 {%0,%1,%2,%3},[%4];"
                 : "=r"(r0), "=r"(r1), "=r"(r2), "=r"(r3) : "r"(a));
}
__device__ __forceinline__ void mma_bf16(float* c, const uint32_t* a, uint32_t b0, uint32_t b1) {
    asm volatile(
        "mma.sync.aligned.m16n8k16.row.col.f32.bf16.bf16.f32 "
        "{%0,%1,%2,%3},{%4,%5,%6,%7},{%8,%9},{%0,%1,%2,%3};"
        : "+f"(c[0]), "+f"(c[1]), "+f"(c[2]), "+f"(c[3])
        : "r"(a[0]), "r"(a[1]), "r"(a[2]), "r"(a[3]), "r"(b0), "r"(b1));
}
__device__ __forceinline__ uint32_t packbf2(float lo, float hi) {
    uint32_t r;
    asm("cvt.rn.bf16x2.f32 %0, %1, %2;" : "=r"(r) : "f"(hi), "f"(lo));
    return r;
}
__device__ __forceinline__ void split_store4(float4 v, bf16* ph, bf16* pl) {
    bf16 h0 = __float2bfloat16_rn(v.x), h1 = __float2bfloat16_rn(v.y),
         h2 = __float2bfloat16_rn(v.z), h3 = __float2bfloat16_rn(v.w);
    ((__nv_bfloat162*)ph)[0] = __halves2bfloat162(h0, h1);
    ((__nv_bfloat162*)ph)[1] = __halves2bfloat162(h2, h3);
    ((__nv_bfloat162*)pl)[0] = __floats2bfloat162_rn(v.x - __bfloat162float(h0), v.y - __bfloat162float(h1));
    ((__nv_bfloat162*)pl)[1] = __floats2bfloat162_rn(v.z - __bfloat162float(h2), v.w - __bfloat162float(h3));
}
__device__ __forceinline__ void split_store2(float v0, float v1, bf16* ph, bf16* pl) {
    bf16 h0 = __float2bfloat16_rn(v0), h1 = __float2bfloat16_rn(v1);
    *(__nv_bfloat162*)ph = __halves2bfloat162(h0, h1);
    *(__nv_bfloat162*)pl = __floats2bfloat162_rn(v0 - __bfloat162float(h0), v1 - __bfloat162float(h1));
}

// ============================================================
// elementwise split: fp32 -> bf16 hi + bf16 lo
// ============================================================
__global__ void split_kernel(const float* __restrict__ x,
                             bf16* __restrict__ xh, bf16* __restrict__ xl, int n4)
{
    int i = blockIdx.x * blockDim.x + threadIdx.x;
    if (i < n4) {
        float4 v = ((const float4*)x)[i];
        split_store4(v, xh + (size_t)i * 4, xl + (size_t)i * 4);
    }
}

// ============================================================
// GEMM C = A@B, bf16-split inputs from gmem, 3-term MMA.
// BM=BN=128, BK=32, 256 threads, warp tile 64x32,
// cp.async 2-stage pipeline.
// ============================================================
#define ALD 40    // 32 + 8 pad (bf16 elems, 80B row = 16B aligned)
#define BLD 136   // 128 + 8 pad (272B row)
#define G_A_ELEMS (128*ALD)    // 5120
#define G_B_ELEMS (32*BLD)     // 4352
#define G_STG (2*G_A_ELEMS + 2*G_B_ELEMS)   // 18944 elems/stage
#define GEMM_SMEM (2 * G_STG * 2)           // 75776 bytes

template<bool SPLIT_OUT>
__global__ __launch_bounds__(256, 1)
void gemm_sp(int M, int N, int K,
             const bf16* __restrict__ Ah_g, const bf16* __restrict__ Al_g,
             const bf16* __restrict__ Bh_g, const bf16* __restrict__ Bl_g,
             float* __restrict__ Cf,
             bf16* __restrict__ Ch, bf16* __restrict__ Cl)
{
    extern __shared__ bf16 smg[];

    const int tid = threadIdx.x;
    const int bm = blockIdx.y, bn = blockIdx.x;
    const size_t aBase = (size_t)bm * 128 * K;
    const size_t bBase = (size_t)bn * 128;

    const int w = tid >> 5, lane = tid & 31;
    const int m0w = (w >> 2) * 64, n0w = (w & 3) * 32;
    const int arow = lane & 15, asel = (lane >> 4) * 8;
    const int brow = (lane & 7) + (lane & 8);
    const int bsel = (lane & 16) >> 1;

    float acc[4][4][4];
    #pragma unroll
    for (int mt = 0; mt < 4; mt++)
        #pragma unroll
        for (int nt = 0; nt < 4; nt++)
            #pragma unroll
            for (int i = 0; i < 4; i++) acc[mt][nt][i] = 0.f;

    const int nk = K / 32;

    // ---- issue helper (inlined twice) ----
    auto issue = [&](int kt, int s) {
        bf16* sAh = smg + (size_t)s * G_STG;
        bf16* sAl = sAh + G_A_ELEMS;
        bf16* sBh = sAl + G_A_ELEMS;
        bf16* sBl = sBh + G_B_ELEMS;
        const int k0 = kt * 32;
        #pragma unroll
        for (int j = 0; j < 2; j++) {
            int c = tid + 256 * j;            // 0..511
            int r = c >> 2, kc = (c & 3) * 8;
            size_t go = aBase + (size_t)r * K + k0 + kc;
            int so = r * ALD + kc;
            cpa16(sptr(sAh + so), Ah_g + go);
            cpa16(sptr(sAl + so), Al_g + go);
        }
        #pragma unroll
        for (int j = 0; j < 2; j++) {
            int c = tid + 256 * j;            // 0..511
            int r = c >> 4, nc = (c & 15) * 8;
            size_t go = bBase + (size_t)(k0 + r) * N + nc;
            int so = r * BLD + nc;
            cpa16(sptr(sBh + so), Bh_g + go);
            cpa16(sptr(sBl + so), Bl_g + go);
        }
        CP_COMMIT();
    };

    issue(0, 0);

    for (int kt = 0; kt < nk; kt++) {
        const int s = kt & 1;
        if (kt + 1 < nk) {
            issue(kt + 1, s ^ 1);
            CP_WAIT(1);
        } else {
            CP_WAIT(0);
        }
        __syncthreads();

        bf16* sAh = smg + (size_t)s * G_STG;
        bf16* sAl = sAh + G_A_ELEMS;
        bf16* sBh = sAl + G_A_ELEMS;
        bf16* sBl = sBh + G_B_ELEMS;

        #pragma unroll
        for (int kk = 0; kk < 2; kk++) {
            uint32_t ah[4][4], al[4][4];
            #pragma unroll
            for (int mt = 0; mt < 4; mt++) {
                int off = (m0w + 16 * mt + arow) * ALD + 16 * kk + asel;
                ldsm4(ah[mt][0], ah[mt][1], ah[mt][2], ah[mt][3], sptr(&sAh[off]));
                ldsm4(al[mt][0], al[mt][1], al[mt][2], al[mt][3], sptr(&sAl[off]));
            }
            uint32_t bh[4][2], bl[4][2];
            #pragma unroll
            for (int nt2 = 0; nt2 < 2; nt2++) {
                int off = (16 * kk + brow) * BLD + n0w + 16 * nt2 + bsel;
                uint32_t r0, r1, r2, r3;
                ldsm4t(r0, r1, r2, r3, sptr(&sBh[off]));
                bh[2*nt2][0] = r0; bh[2*nt2][1] = r1; bh[2*nt2+1][0] = r2; bh[2*nt2+1][1] = r3;
                ldsm4t(r0, r1, r2, r3, sptr(&sBl[off]));
                bl[2*nt2][0] = r0; bl[2*nt2][1] = r1; bl[2*nt2+1][0] = r2; bl[2*nt2+1][1] = r3;
            }
            #pragma unroll
            for (int mt = 0; mt < 4; mt++)
                #pragma unroll
                for (int nt = 0; nt < 4; nt++) {
                    mma_bf16(acc[mt][nt], ah[mt], bh[nt][0], bh[nt][1]);
                    mma_bf16(acc[mt][nt], ah[mt], bl[nt][0], bl[nt][1]);
                    mma_bf16(acc[mt][nt], al[mt], bh[nt][0], bh[nt][1]);
                }
        }
        __syncthreads();
    }

    // epilogue
    const int g = lane >> 2, t = lane & 3;
    #pragma unroll
    for (int mt = 0; mt < 4; mt++)
        #pragma unroll
        for (int nt = 0; nt < 4; nt++) {
            size_t r0 = (size_t)bm * 128 + m0w + 16 * mt + g;
            size_t c0 = (size_t)bn * 128 + n0w + 8 * nt + 2 * t;
            if (SPLIT_OUT) {
                split_store2(acc[mt][nt][0], acc[mt][nt][1], &Ch[r0 * N + c0], &Cl[r0 * N + c0]);
                split_store2(acc[mt][nt][2], acc[mt][nt][3], &Ch[(r0 + 8) * N + c0], &Cl[(r0 + 8) * N + c0]);
            } else {
                float2 u; u.x = acc[mt][nt][0]; u.y = acc[mt][nt][1];
                *(float2*)&Cf[r0 * N + c0] = u;
                float2 v; v.x = acc[mt][nt][2]; v.y = acc[mt][nt][3];
                *(float2*)&Cf[(r0 + 8) * N + c0] = v;
            }
        }
}

// ============================================================
// Flash attention, bf16-split MMA, cp.async 2-stage KV pipeline.
// grid (SS/128, NHEAD, BB), 256 threads (8 warps), 16 q-rows/warp,
// KV tile = 64. Writes ctx as split bf16.
// ============================================================
#define KLD 136
#define A_STG (4 * 64 * KLD)                 // 34816 elems/stage
#define ATTN_SMEM (2 * A_STG * 2 + 2 * 64 * 4)   // 139776 bytes

__global__ __launch_bounds__(256, 1)
void attn_mma(const bf16* __restrict__ Qh, const bf16* __restrict__ Ql,
              const bf16* __restrict__ Kh, const bf16* __restrict__ Kl,
              const bf16* __restrict__ Vh, const bf16* __restrict__ Vl,
              const float* __restrict__ maskp,
              bf16* __restrict__ ctxh, bf16* __restrict__ ctxl)
{
    extern __shared__ bf16 sma[];
    float* mbuf = (float*)(sma + 2 * A_STG);   // [2][64]

    const int tid = threadIdx.x;
    const int w = tid >> 5, lane = tid & 31;
    const int g = lane >> 2, t = lane & 3;
    const int h = blockIdx.y, b = blockIdx.z, kh = h >> 2;
    const size_t qrow0 = (size_t)b * SS + blockIdx.x * 128 + w * 16;

    const float scale = 0.08838834764831845f;  // 1/sqrt(128)

    // ---- KV tile issue ----
    auto issue = [&](int kt, int s) {
        bf16* sKh = sma + (size_t)s * A_STG;
        bf16* sKl = sKh + 64 * KLD;
        bf16* sVh = sKl + 64 * KLD;
        bf16* sVl = sVh + 64 * KLD;
        const int kv0 = kt * 64;
        const size_t gbase = ((size_t)b * SS + kv0) * KVDIM + kh * HDIM;
        #pragma unroll
        for (int j = 0; j < 4; j++) {
            int id = tid + 256 * j;          // 0..1023
            int r = id >> 4, c8 = (id & 15) * 8;
            size_t go = gbase + (size_t)r * KVDIM + c8;
            int so = r * KLD + c8;
            cpa16(sptr(sKh + so), Kh + go);
            cpa16(sptr(sKl + so), Kl + go);
            cpa16(sptr(sVh + so), Vh + go);
            cpa16(sptr(sVl + so), Vl + go);
        }
        if (tid < 64) mbuf[s * 64 + tid] = (1.0f - maskp[(size_t)b * SS + kv0 + tid]) * -1e9f;
        CP_COMMIT();
    };

    // preload Q fragments (kept for all 32 KV tiles)
    uint32_t qfh[8][4], qfl[8][4];
    {
        const bf16* qh0 = Qh + qrow0 * EMBED + h * HDIM;
        const bf16* ql0 = Ql + qrow0 * EMBED + h * HDIM;
        #pragma unroll
        for (int kk = 0; kk < 8; kk++) {
            int c0 = 16 * kk + 2 * t;
            qfh[kk][0] = *(const uint32_t*)(qh0 + (size_t)g * EMBED + c0);
            qfh[kk][1] = *(const uint32_t*)(qh0 + (size_t)(g + 8) * EMBED + c0);
            qfh[kk][2] = *(const uint32_t*)(qh0 + (size_t)g * EMBED + c0 + 8);
            qfh[kk][3] = *(const uint32_t*)(qh0 + (size_t)(g + 8) * EMBED + c0 + 8);
            qfl[kk][0] = *(const uint32_t*)(ql0 + (size_t)g * EMBED + c0);
            qfl[kk][1] = *(const uint32_t*)(ql0 + (size_t)(g + 8) * EMBED + c0);
            qfl[kk][2] = *(const uint32_t*)(ql0 + (size_t)g * EMBED + c0 + 8);
            qfl[kk][3] = *(const uint32_t*)(ql0 + (size_t)(g + 8) * EMBED + c0 + 8);
        }
    }

    float o[16][4];
    #pragma unroll
    for (int nt = 0; nt < 16; nt++)
        #pragma unroll
        for (int i = 0; i < 4; i++) o[nt][i] = 0.f;
    float m0 = -1e30f, m1 = -1e30f, l0 = 0.f, l1 = 0.f;

    const int vrow = (lane & 7) + (lane & 8);
    const int vsel = (lane & 16) >> 1;

    issue(0, 0);

    for (int kt = 0; kt < SS / 64; kt++) {
        const int s = kt & 1;
        if (kt + 1 < SS / 64) {
            issue(kt + 1, s ^ 1);
            CP_WAIT(1);
        } else {
            CP_WAIT(0);
        }
        __syncthreads();

        bf16* sKh = sma + (size_t)s * A_STG;
        bf16* sKl = sKh + 64 * KLD;
        bf16* sVh = sKl + 64 * KLD;
        bf16* sVl = sVh + 64 * KLD;
        float* mb = mbuf + s * 64;

        // ---- S = Q K^T ----
        float sc[8][4];
        #pragma unroll
        for (int nt = 0; nt < 8; nt++)
            #pragma unroll
            for (int i = 0; i < 4; i++) sc[nt][i] = 0.f;

        #pragma unroll
        for (int kk = 0; kk < 8; kk++) {
            #pragma unroll
            for (int nt2 = 0; nt2 < 4; nt2++) {
                int row = 16 * nt2 + (lane & 15);
                int col = 16 * kk + (lane >> 4) * 8;
                uint32_t r0, r1, r2, r3, u0, u1, u2, u3;
                ldsm4(r0, r1, r2, r3, sptr(&sKh[row * KLD + col]));
                ldsm4(u0, u1, u2, u3, sptr(&sKl[row * KLD + col]));
                mma_bf16(sc[2*nt2],   qfh[kk], r0, r2);
                mma_bf16(sc[2*nt2+1], qfh[kk], r1, r3);
                mma_bf16(sc[2*nt2],   qfh[kk], u0, u2);
                mma_bf16(sc[2*nt2+1], qfh[kk], u1, u3);
                mma_bf16(sc[2*nt2],   qfl[kk], r0, r2);
                mma_bf16(sc[2*nt2+1], qfl[kk], r1, r3);
            }
        }

        // ---- scale + mask + online softmax ----
        float rm0 = -1e30f, rm1 = -1e30f;
        #pragma unroll
        for (int nt = 0; nt < 8; nt++) {
            float cb0 = mb[8 * nt + 2 * t];
            float cb1 = mb[8 * nt + 2 * t + 1];
            sc[nt][0] = sc[nt][0] * scale + cb0;
            sc[nt][1] = sc[nt][1] * scale + cb1;
            sc[nt][2] = sc[nt][2] * scale + cb0;
            sc[nt][3] = sc[nt][3] * scale + cb1;
            rm0 = fmaxf(rm0, fmaxf(sc[nt][0], sc[nt][1]));
            rm1 = fmaxf(rm1, fmaxf(sc[nt][2], sc[nt][3]));
        }
        rm0 = fmaxf(rm0, __shfl_xor_sync(0xffffffffu, rm0, 1));
        rm0 = fmaxf(rm0, __shfl_xor_sync(0xffffffffu, rm0, 2));
        rm1 = fmaxf(rm1, __shfl_xor_sync(0xffffffffu, rm1, 1));
        rm1 = fmaxf(rm1, __shfl_xor_sync(0xffffffffu, rm1, 2));
        float mn0 = fmaxf(m0, rm0), mn1 = fmaxf(m1, rm1);
        float a0 = __expf(m0 - mn0), a1 = __expf(m1 - mn1);
        m0 = mn0; m1 = mn1;

        float ps0 = 0.f, ps1 = 0.f;
        #pragma unroll
        for (int nt = 0; nt < 8; nt++) {
            sc[nt][0] = __expf(sc[nt][0] - mn0);
            sc[nt][1] = __expf(sc[nt][1] - mn0);
            sc[nt][2] = __expf(sc[nt][2] - mn1);
            sc[nt][3] = __expf(sc[nt][3] - mn1);
            ps0 += sc[nt][0] + sc[nt][1];
            ps1 += sc[nt][2] + sc[nt][3];
        }
        ps0 += __shfl_xor_sync(0xffffffffu, ps0, 1);
        ps0 += __shfl_xor_sync(0xffffffffu, ps0, 2);
        ps1 += __shfl_xor_sync(0xffffffffu, ps1, 1);
        ps1 += __shfl_xor_sync(0xffffffffu, ps1, 2);
        l0 = l0 * a0 + ps0;
        l1 = l1 * a1 + ps1;

        #pragma unroll
        for (int nt = 0; nt < 16; nt++) {
            o[nt][0] *= a0; o[nt][1] *= a0;
            o[nt][2] *= a1; o[nt][3] *= a1;
        }

        // ---- pack P fragments (hi/lo split, C-frag -> A-frag remap) ----
        uint32_t pah[4][4], pal[4][4];
        #pragma unroll
        for (int j = 0; j < 4; j++) {
            #pragma unroll
            for (int half = 0; half < 2; half++) {
                float v0 = sc[2*j + half][0], v1 = sc[2*j + half][1];
                float v2 = sc[2*j + half][2], v3 = sc[2*j + half][3];
                float h0 = __bfloat162float(__float2bfloat16_rn(v0));
                float h1 = __bfloat162float(__float2bfloat16_rn(v1));
                float h2 = __bfloat162float(__float2bfloat16_rn(v2));
                float h3 = __bfloat162float(__float2bfloat16_rn(v3));
                pah[j][2*half + 0] = packbf2(h0, h1);
                pah[j][2*half + 1] = packbf2(h2, h3);
                pal[j][2*half + 0] = packbf2(v0 - h0, v1 - h1);
                pal[j][2*half + 1] = packbf2(v2 - h2, v3 - h3);
            }
        }

        // ---- O += P V ----
        #pragma unroll
        for (int j = 0; j < 4; j++) {
            #pragma unroll
            for (int nt2 = 0; nt2 < 8; nt2++) {
                int row = 16 * j + vrow;
                int col = 16 * nt2 + vsel;
                uint32_t r0, r1, r2, r3, u0, u1, u2, u3;
                ldsm4t(r0, r1, r2, r3, sptr(&sVh[row * KLD + col]));
                ldsm4t(u0, u1, u2, u3, sptr(&sVl[row * KLD + col]));
                mma_bf16(o[2*nt2],   pah[j], r0, r1);
                mma_bf16(o[2*nt2+1], pah[j], r2, r3);
                mma_bf16(o[2*nt2],   pah[j], u0, u1);
                mma_bf16(o[2*nt2+1], pah[j], u2, u3);
                mma_bf16(o[2*nt2],   pal[j], r0, r1);
                mma_bf16(o[2*nt2+1], pal[j], r2, r3);
            }
        }
        __syncthreads();
    }

    // ---- epilogue: write ctx split bf16 ----
    float i0 = 1.0f / l0, i1 = 1.0f / l1;
    size_t base0 = (qrow0 + g) * EMBED + h * HDIM + 2 * t;
    size_t base1 = (qrow0 + g + 8) * EMBED + h * HDIM + 2 * t;
    #pragma unroll
    for (int nt = 0; nt < 16; nt++) {
        split_store2(o[nt][0] * i0, o[nt][1] * i0, &ctxh[base0 + 8 * nt], &ctxl[base0 + 8 * nt]);
        split_store2(o[nt][2] * i1, o[nt][3] * i1, &ctxh[base1 + 8 * nt], &ctxl[base1 + 8 * nt]);
    }
}

// ============================================================
// launcher
// ============================================================
extern "C" void kernel_launch(void* const* d_in, const int* in_sizes, int n_in,
                              void* d_out, int out_size)
{
    const float* query = (const float*)d_in[0];
    const float* key   = (const float*)d_in[1];
    const float* value = (const float*)d_in[2];
    const float* mask  = (const float*)d_in[3];
    const float* Wq    = (const float*)d_in[4];
    const float* Wk    = (const float*)d_in[5];
    const float* Wv    = (const float*)d_in[6];
    const float* Wo    = (const float*)d_in[7];
    float* out = (float*)d_out;

    bf16 *inh, *inl, *wh, *wl, *qh, *ql, *kh, *kl, *vh, *vl, *ctxh, *ctxl;
    cudaGetSymbolAddress((void**)&inh, g_inh);
    cudaGetSymbolAddress((void**)&inl, g_inl);
    cudaGetSymbolAddress((void**)&wh,  g_wh);
    cudaGetSymbolAddress((void**)&wl,  g_wl);
    cudaGetSymbolAddress((void**)&qh,  g_qh);
    cudaGetSymbolAddress((void**)&ql,  g_ql);
    cudaGetSymbolAddress((void**)&kh,  g_kh);
    cudaGetSymbolAddress((void**)&kl,  g_kl);
    cudaGetSymbolAddress((void**)&vh,  g_vh);
    cudaGetSymbolAddress((void**)&vl,  g_vl);
    cudaGetSymbolAddress((void**)&ctxh, g_ctxh);
    cudaGetSymbolAddress((void**)&ctxl, g_ctxl);

    cudaFuncSetAttribute(attn_mma, cudaFuncAttributeMaxDynamicSharedMemorySize, ATTN_SMEM);
    cudaFuncSetAttribute(gemm_sp<true>,  cudaFuncAttributeMaxDynamicSharedMemorySize, GEMM_SMEM);
    cudaFuncSetAttribute(gemm_sp<false>, cudaFuncAttributeMaxDynamicSharedMemorySize, GEMM_SMEM);

    dim3 blk(256);

    // ---- split passes ----
    {
        int n4;
        n4 = IN_STRIDE / 4;
        split_kernel<<<(n4 + 255) / 256, blk>>>(query, inh + 0 * (size_t)IN_STRIDE, inl + 0 * (size_t)IN_STRIDE, n4);
        split_kernel<<<(n4 + 255) / 256, blk>>>(key,   inh + 1 * (size_t)IN_STRIDE, inl + 1 * (size_t)IN_STRIDE, n4);
        split_kernel<<<(n4 + 255) / 256, blk>>>(value, inh + 2 * (size_t)IN_STRIDE, inl + 2 * (size_t)IN_STRIDE, n4);
        n4 = (EMBED * EMBED) / 4;
        split_kernel<<<(n4 + 255) / 256, blk>>>(Wq, wh + WQ_OFF, wl + WQ_OFF, n4);
        split_kernel<<<(n4 + 255) / 256, blk>>>(Wo, wh + WO_OFF, wl + WO_OFF, n4);
        n4 = (EMBED * KVDIM) / 4;
        split_kernel<<<(n4 + 255) / 256, blk>>>(Wk, wh + WK_OFF, wl + WK_OFF, n4);
        split_kernel<<<(n4 + 255) / 256, blk>>>(Wv, wh + WV_OFF, wl + WV_OFF, n4);
    }

    // ---- projections ----
    gemm_sp<true><<<dim3(EMBED / 128, MROWS / 128), blk, GEMM_SMEM>>>(
        MROWS, EMBED, EMBED,
        inh + 0 * (size_t)IN_STRIDE, inl + 0 * (size_t)IN_STRIDE,
        wh + WQ_OFF, wl + WQ_OFF, nullptr, qh, ql);
    gemm_sp<true><<<dim3(KVDIM / 128, MROWS / 128), blk, GEMM_SMEM>>>(
        MROWS, KVDIM, EMBED,
        inh + 1 * (size_t)IN_STRIDE, inl + 1 * (size_t)IN_STRIDE,
        wh + WK_OFF, wl + WK_OFF, nullptr, kh, kl);
    gemm_sp<true><<<dim3(KVDIM / 128, MROWS / 128), blk, GEMM_SMEM>>>(
        MROWS, KVDIM, EMBED,
        inh + 2 * (size_t)IN_STRIDE, inl + 2 * (size_t)IN_STRIDE,
        wh + WV_OFF, wl + WV_OFF, nullptr, vh, vl);

    // ---- fused attention ----
    attn_mma<<<dim3(SS / 128, NHEAD, BB), blk, ATTN_SMEM>>>(
        qh, ql, kh, kl, vh, vl, mask, ctxh, ctxl);

    // ---- output projection (fp32 out) ----
    gemm_sp<false><<<dim3(EMBED / 128, MROWS / 128), blk, GEMM_SMEM>>>(
        MROWS, EMBED, EMBED, ctxh, ctxl, wh + WO_OFF, wl + WO_OFF, out, nullptr, nullptr);
}

// round 5
// speedup vs baseline: 3.9000x; 1.0579x over previous
#include <cuda_runtime.h>
#include <cuda_bf16.h>
#include <cstdint>

// Problem constants
#define EMBED 2048
#define NHEAD 16
#define NKV   4
#define HDIM  128
#define BB    2
#define SS    2048
#define MROWS (BB*SS)          // 4096
#define KVDIM (NKV*HDIM)       // 512

typedef __nv_bfloat16 bf16;

// -------- scratch (no allocation allowed) --------
#define IN_STRIDE (MROWS * EMBED)
__device__ bf16 g_inh[3 * IN_STRIDE];
__device__ bf16 g_inl[3 * IN_STRIDE];
#define WQ_OFF 0
#define WK_OFF (EMBED*EMBED)
#define WV_OFF (WK_OFF + EMBED*KVDIM)
#define WO_OFF (WV_OFF + EMBED*KVDIM)
#define W_TOTAL (WO_OFF + EMBED*EMBED)
__device__ bf16 g_wh[W_TOTAL];
__device__ bf16 g_wl[W_TOTAL];
__device__ bf16 g_qh[MROWS * EMBED];
__device__ bf16 g_ql[MROWS * EMBED];
__device__ bf16 g_kh[MROWS * KVDIM];
__device__ bf16 g_kl[MROWS * KVDIM];
__device__ bf16 g_vh[MROWS * KVDIM];
__device__ bf16 g_vl[MROWS * KVDIM];
__device__ bf16 g_ctxh[MROWS * EMBED];
__device__ bf16 g_ctxl[MROWS * EMBED];

// ======================= helpers =======================
__device__ __forceinline__ uint32_t sptr(const void* p) {
    return (uint32_t)__cvta_generic_to_shared(p);
}
__device__ __forceinline__ void cpa16(uint32_t dst, const void* src) {
    asm volatile("cp.async.cg.shared.global [%0], [%1], 16;" :: "r"(dst), "l"(src));
}
#define CP_COMMIT() asm volatile("cp.async.commit_group;")
#define CP_WAIT(n)  asm volatile("cp.async.wait_group %0;" :: "n"(n))

__device__ __forceinline__ void ldsm4(uint32_t& r0, uint32_t& r1, uint32_t& r2, uint32_t& r3, uint32_t a) {
    asm volatile("ldmatrix.sync.aligned.m8n8.x4.shared.b16 {%0,%1,%2,%3},[%4];"
                 : "=r"(r0), "=r"(r1), "=r"(r2), "=r"(r3) : "r"(a));
}
__device__ __forceinline__ void ldsm4t(uint32_t& r0, uint32_t& r1, uint32_t& r2, uint32_t& r3, uint32_t a) {
    asm volatile("ldmatrix.sync.aligned.m8n8.x4.trans.shared.b16 {%0,%1,%2,%3},[%4];"
                 : "=r"(r0), "=r"(r1), "=r"(r2), "=r"(r3) : "r"(a));
}
__device__ __forceinline__ void mma_bf16(float* c, const uint32_t* a, uint32_t b0, uint32_t b1) {
    asm volatile(
        "mma.sync.aligned.m16n8k16.row.col.f32.bf16.bf16.f32 "
        "{%0,%1,%2,%3},{%4,%5,%6,%7},{%8,%9},{%0,%1,%2,%3};"
        : "+f"(c[0]), "+f"(c[1]), "+f"(c[2]), "+f"(c[3])
        : "r"(a[0]), "r"(a[1]), "r"(a[2]), "r"(a[3]), "r"(b0), "r"(b1));
}
__device__ __forceinline__ uint32_t packbf2(float lo, float hi) {
    uint32_t r;
    asm("cvt.rn.bf16x2.f32 %0, %1, %2;" : "=r"(r) : "f"(hi), "f"(lo));
    return r;
}
__device__ __forceinline__ void split_store4(float4 v, bf16* ph, bf16* pl) {
    bf16 h0 = __float2bfloat16_rn(v.x), h1 = __float2bfloat16_rn(v.y),
         h2 = __float2bfloat16_rn(v.z), h3 = __float2bfloat16_rn(v.w);
    ((__nv_bfloat162*)ph)[0] = __halves2bfloat162(h0, h1);
    ((__nv_bfloat162*)ph)[1] = __halves2bfloat162(h2, h3);
    ((__nv_bfloat162*)pl)[0] = __floats2bfloat162_rn(v.x - __bfloat162float(h0), v.y - __bfloat162float(h1));
    ((__nv_bfloat162*)pl)[1] = __floats2bfloat162_rn(v.z - __bfloat162float(h2), v.w - __bfloat162float(h3));
}
__device__ __forceinline__ void split_store2(float v0, float v1, bf16* ph, bf16* pl) {
    bf16 h0 = __float2bfloat16_rn(v0), h1 = __float2bfloat16_rn(v1);
    *(__nv_bfloat162*)ph = __halves2bfloat162(h0, h1);
    *(__nv_bfloat162*)pl = __floats2bfloat162_rn(v0 - __bfloat162float(h0), v1 - __bfloat162float(h1));
}

// ============================================================
// elementwise split: fp32 -> bf16 hi + bf16 lo
// ============================================================
__global__ void split_kernel(const float* __restrict__ x,
                             bf16* __restrict__ xh, bf16* __restrict__ xl, int n4)
{
    int i = blockIdx.x * blockDim.x + threadIdx.x;
    if (i < n4) {
        float4 v = ((const float4*)x)[i];
        split_store4(v, xh + (size_t)i * 4, xl + (size_t)i * 4);
    }
}

// ============================================================
// GEMM C = A@B, bf16-split inputs, 3-term MMA.
// BM=BN=128, BK=64, 256 threads, warp tile 64x32,
// cp.async 2-stage pipeline (sync every 192 MMAs/warp).
// ============================================================
#define ALD 72    // 64 + 8 pad
#define BLD 136   // 128 + 8 pad
#define G_A_ELEMS (128*ALD)    // 9216
#define G_B_ELEMS (64*BLD)     // 8704
#define G_STG (2*G_A_ELEMS + 2*G_B_ELEMS)   // 35840 elems/stage
#define GEMM_SMEM (2 * G_STG * 2)           // 143360 bytes

template<bool SPLIT_OUT>
__global__ __launch_bounds__(256, 1)
void gemm_sp(int M, int N, int K,
             const bf16* __restrict__ Ah_g, const bf16* __restrict__ Al_g,
             const bf16* __restrict__ Bh_g, const bf16* __restrict__ Bl_g,
             float* __restrict__ Cf,
             bf16* __restrict__ Ch, bf16* __restrict__ Cl)
{
    extern __shared__ bf16 smg[];

    const int tid = threadIdx.x;
    const int bm = blockIdx.y, bn = blockIdx.x;
    const size_t aBase = (size_t)bm * 128 * K;
    const size_t bBase = (size_t)bn * 128;

    const int w = tid >> 5, lane = tid & 31;
    const int m0w = (w >> 2) * 64, n0w = (w & 3) * 32;
    const int arow = lane & 15, asel = (lane >> 4) * 8;
    const int brow = (lane & 7) + (lane & 8);
    const int bsel = (lane & 16) >> 1;

    float acc[4][4][4];
    #pragma unroll
    for (int mt = 0; mt < 4; mt++)
        #pragma unroll
        for (int nt = 0; nt < 4; nt++)
            #pragma unroll
            for (int i = 0; i < 4; i++) acc[mt][nt][i] = 0.f;

    const int nk = K / 64;

    auto issue = [&](int kt, int s) {
        bf16* sAh = smg + (size_t)s * G_STG;
        bf16* sAl = sAh + G_A_ELEMS;
        bf16* sBh = sAl + G_A_ELEMS;
        bf16* sBl = sBh + G_B_ELEMS;
        const int k0 = kt * 64;
        #pragma unroll
        for (int j = 0; j < 4; j++) {
            int c = tid + 256 * j;            // 0..1023
            int r = c >> 3, kc = (c & 7) * 8;
            size_t go = aBase + (size_t)r * K + k0 + kc;
            int so = r * ALD + kc;
            cpa16(sptr(sAh + so), Ah_g + go);
            cpa16(sptr(sAl + so), Al_g + go);
        }
        #pragma unroll
        for (int j = 0; j < 4; j++) {
            int c = tid + 256 * j;            // 0..1023
            int r = c >> 4, nc = (c & 15) * 8;
            size_t go = bBase + (size_t)(k0 + r) * N + nc;
            int so = r * BLD + nc;
            cpa16(sptr(sBh + so), Bh_g + go);
            cpa16(sptr(sBl + so), Bl_g + go);
        }
        CP_COMMIT();
    };

    issue(0, 0);

    for (int kt = 0; kt < nk; kt++) {
        const int s = kt & 1;
        if (kt + 1 < nk) {
            issue(kt + 1, s ^ 1);
            CP_WAIT(1);
        } else {
            CP_WAIT(0);
        }
        __syncthreads();

        bf16* sAh = smg + (size_t)s * G_STG;
        bf16* sAl = sAh + G_A_ELEMS;
        bf16* sBh = sAl + G_A_ELEMS;
        bf16* sBl = sBh + G_B_ELEMS;

        #pragma unroll
        for (int kk = 0; kk < 4; kk++) {
            uint32_t ah[4][4], al[4][4];
            #pragma unroll
            for (int mt = 0; mt < 4; mt++) {
                int off = (m0w + 16 * mt + arow) * ALD + 16 * kk + asel;
                ldsm4(ah[mt][0], ah[mt][1], ah[mt][2], ah[mt][3], sptr(&sAh[off]));
                ldsm4(al[mt][0], al[mt][1], al[mt][2], al[mt][3], sptr(&sAl[off]));
            }
            uint32_t bh[4][2], bl[4][2];
            #pragma unroll
            for (int nt2 = 0; nt2 < 2; nt2++) {
                int off = (16 * kk + brow) * BLD + n0w + 16 * nt2 + bsel;
                uint32_t r0, r1, r2, r3;
                ldsm4t(r0, r1, r2, r3, sptr(&sBh[off]));
                bh[2*nt2][0] = r0; bh[2*nt2][1] = r1; bh[2*nt2+1][0] = r2; bh[2*nt2+1][1] = r3;
                ldsm4t(r0, r1, r2, r3, sptr(&sBl[off]));
                bl[2*nt2][0] = r0; bl[2*nt2][1] = r1; bl[2*nt2+1][0] = r2; bl[2*nt2+1][1] = r3;
            }
            #pragma unroll
            for (int mt = 0; mt < 4; mt++)
                #pragma unroll
                for (int nt = 0; nt < 4; nt++) {
                    mma_bf16(acc[mt][nt], ah[mt], bh[nt][0], bh[nt][1]);
                    mma_bf16(acc[mt][nt], ah[mt], bl[nt][0], bl[nt][1]);
                    mma_bf16(acc[mt][nt], al[mt], bh[nt][0], bh[nt][1]);
                }
        }
        __syncthreads();
    }

    // epilogue
    const int g = lane >> 2, t = lane & 3;
    #pragma unroll
    for (int mt = 0; mt < 4; mt++)
        #pragma unroll
        for (int nt = 0; nt < 4; nt++) {
            size_t r0 = (size_t)bm * 128 + m0w + 16 * mt + g;
            size_t c0 = (size_t)bn * 128 + n0w + 8 * nt + 2 * t;
            if (SPLIT_OUT) {
                split_store2(acc[mt][nt][0], acc[mt][nt][1], &Ch[r0 * N + c0], &Cl[r0 * N + c0]);
                split_store2(acc[mt][nt][2], acc[mt][nt][3], &Ch[(r0 + 8) * N + c0], &Cl[(r0 + 8) * N + c0]);
            } else {
                float2 u; u.x = acc[mt][nt][0]; u.y = acc[mt][nt][1];
                *(float2*)&Cf[r0 * N + c0] = u;
                float2 v; v.x = acc[mt][nt][2]; v.y = acc[mt][nt][3];
                *(float2*)&Cf[(r0 + 8) * N + c0] = v;
            }
        }
}

// ============================================================
// Flash attention, bf16-split MMA.
// 128 threads (4 warps), 64 q-rows/CTA (16/warp), KV tile 32,
// 2-stage cp.async, smem ~70KB -> 2 CTAs/SM.
// grid (SS/64, NHEAD, BB).
// ============================================================
#define KTILE 32
#define KLD 136
#define A_STG (4 * KTILE * KLD)                 // 17408 elems/stage
#define ATTN_SMEM (2 * A_STG * 2 + 2 * KTILE * 4)   // 69888 bytes

__global__ __launch_bounds__(128, 2)
void attn_mma(const bf16* __restrict__ Qh, const bf16* __restrict__ Ql,
              const bf16* __restrict__ Kh, const bf16* __restrict__ Kl,
              const bf16* __restrict__ Vh, const bf16* __restrict__ Vl,
              const float* __restrict__ maskp,
              bf16* __restrict__ ctxh, bf16* __restrict__ ctxl)
{
    extern __shared__ bf16 sma[];
    float* mbuf = (float*)(sma + 2 * A_STG);   // [2][32]

    const int tid = threadIdx.x;
    const int w = tid >> 5, lane = tid & 31;
    const int g = lane >> 2, t = lane & 3;
    const int h = blockIdx.y, b = blockIdx.z, kh = h >> 2;
    const size_t qrow0 = (size_t)b * SS + blockIdx.x * 64 + w * 16;

    const float scale = 0.08838834764831845f;  // 1/sqrt(128)

    auto issue = [&](int kt, int s) {
        bf16* sKh = sma + (size_t)s * A_STG;
        bf16* sKl = sKh + KTILE * KLD;
        bf16* sVh = sKl + KTILE * KLD;
        bf16* sVl = sVh + KTILE * KLD;
        const int kv0 = kt * KTILE;
        const size_t gbase = ((size_t)b * SS + kv0) * KVDIM + kh * HDIM;
        #pragma unroll
        for (int j = 0; j < 4; j++) {
            int id = tid + 128 * j;          // 0..511
            int r = id >> 4, c8 = (id & 15) * 8;
            size_t go = gbase + (size_t)r * KVDIM + c8;
            int so = r * KLD + c8;
            cpa16(sptr(sKh + so), Kh + go);
            cpa16(sptr(sKl + so), Kl + go);
            cpa16(sptr(sVh + so), Vh + go);
            cpa16(sptr(sVl + so), Vl + go);
        }
        if (tid < KTILE) mbuf[s * KTILE + tid] = (1.0f - maskp[(size_t)b * SS + kv0 + tid]) * -1e9f;
        CP_COMMIT();
    };

    // preload Q fragments (kept for all KV tiles)
    uint32_t qfh[8][4], qfl[8][4];
    {
        const bf16* qh0 = Qh + qrow0 * EMBED + h * HDIM;
        const bf16* ql0 = Ql + qrow0 * EMBED + h * HDIM;
        #pragma unroll
        for (int kk = 0; kk < 8; kk++) {
            int c0 = 16 * kk + 2 * t;
            qfh[kk][0] = *(const uint32_t*)(qh0 + (size_t)g * EMBED + c0);
            qfh[kk][1] = *(const uint32_t*)(qh0 + (size_t)(g + 8) * EMBED + c0);
            qfh[kk][2] = *(const uint32_t*)(qh0 + (size_t)g * EMBED + c0 + 8);
            qfh[kk][3] = *(const uint32_t*)(qh0 + (size_t)(g + 8) * EMBED + c0 + 8);
            qfl[kk][0] = *(const uint32_t*)(ql0 + (size_t)g * EMBED + c0);
            qfl[kk][1] = *(const uint32_t*)(ql0 + (size_t)(g + 8) * EMBED + c0);
            qfl[kk][2] = *(const uint32_t*)(ql0 + (size_t)g * EMBED + c0 + 8);
            qfl[kk][3] = *(const uint32_t*)(ql0 + (size_t)(g + 8) * EMBED + c0 + 8);
        }
    }

    float o[16][4];
    #pragma unroll
    for (int nt = 0; nt < 16; nt++)
        #pragma unroll
        for (int i = 0; i < 4; i++) o[nt][i] = 0.f;
    float m0 = -1e30f, m1 = -1e30f, l0 = 0.f, l1 = 0.f;

    const int vrow = (lane & 7) + (lane & 8);
    const int vsel = (lane & 16) >> 1;

    issue(0, 0);

    const int NKT = SS / KTILE;   // 64
    for (int kt = 0; kt < NKT; kt++) {
        const int s = kt & 1;
        if (kt + 1 < NKT) {
            issue(kt + 1, s ^ 1);
            CP_WAIT(1);
        } else {
            CP_WAIT(0);
        }
        __syncthreads();

        bf16* sKh = sma + (size_t)s * A_STG;
        bf16* sKl = sKh + KTILE * KLD;
        bf16* sVh = sKl + KTILE * KLD;
        bf16* sVl = sVh + KTILE * KLD;
        float* mb = mbuf + s * KTILE;

        // ---- S = Q K^T ---- (16 x 32 per warp)
        float sc[4][4];
        #pragma unroll
        for (int nt = 0; nt < 4; nt++)
            #pragma unroll
            for (int i = 0; i < 4; i++) sc[nt][i] = 0.f;

        #pragma unroll
        for (int kk = 0; kk < 8; kk++) {
            #pragma unroll
            for (int nt2 = 0; nt2 < 2; nt2++) {
                int row = 16 * nt2 + (lane & 15);
                int col = 16 * kk + (lane >> 4) * 8;
                uint32_t r0, r1, r2, r3, u0, u1, u2, u3;
                ldsm4(r0, r1, r2, r3, sptr(&sKh[row * KLD + col]));
                ldsm4(u0, u1, u2, u3, sptr(&sKl[row * KLD + col]));
                mma_bf16(sc[2*nt2],   qfh[kk], r0, r2);
                mma_bf16(sc[2*nt2+1], qfh[kk], r1, r3);
                mma_bf16(sc[2*nt2],   qfh[kk], u0, u2);
                mma_bf16(sc[2*nt2+1], qfh[kk], u1, u3);
                mma_bf16(sc[2*nt2],   qfl[kk], r0, r2);
                mma_bf16(sc[2*nt2+1], qfl[kk], r1, r3);
            }
        }

        // ---- scale + mask + online softmax ----
        float rm0 = -1e30f, rm1 = -1e30f;
        #pragma unroll
        for (int nt = 0; nt < 4; nt++) {
            float cb0 = mb[8 * nt + 2 * t];
            float cb1 = mb[8 * nt + 2 * t + 1];
            sc[nt][0] = sc[nt][0] * scale + cb0;
            sc[nt][1] = sc[nt][1] * scale + cb1;
            sc[nt][2] = sc[nt][2] * scale + cb0;
            sc[nt][3] = sc[nt][3] * scale + cb1;
            rm0 = fmaxf(rm0, fmaxf(sc[nt][0], sc[nt][1]));
            rm1 = fmaxf(rm1, fmaxf(sc[nt][2], sc[nt][3]));
        }
        rm0 = fmaxf(rm0, __shfl_xor_sync(0xffffffffu, rm0, 1));
        rm0 = fmaxf(rm0, __shfl_xor_sync(0xffffffffu, rm0, 2));
        rm1 = fmaxf(rm1, __shfl_xor_sync(0xffffffffu, rm1, 1));
        rm1 = fmaxf(rm1, __shfl_xor_sync(0xffffffffu, rm1, 2));
        float mn0 = fmaxf(m0, rm0), mn1 = fmaxf(m1, rm1);
        float a0 = __expf(m0 - mn0), a1 = __expf(m1 - mn1);
        m0 = mn0; m1 = mn1;

        float ps0 = 0.f, ps1 = 0.f;
        #pragma unroll
        for (int nt = 0; nt < 4; nt++) {
            sc[nt][0] = __expf(sc[nt][0] - mn0);
            sc[nt][1] = __expf(sc[nt][1] - mn0);
            sc[nt][2] = __expf(sc[nt][2] - mn1);
            sc[nt][3] = __expf(sc[nt][3] - mn1);
            ps0 += sc[nt][0] + sc[nt][1];
            ps1 += sc[nt][2] + sc[nt][3];
        }
        ps0 += __shfl_xor_sync(0xffffffffu, ps0, 1);
        ps0 += __shfl_xor_sync(0xffffffffu, ps0, 2);
        ps1 += __shfl_xor_sync(0xffffffffu, ps1, 1);
        ps1 += __shfl_xor_sync(0xffffffffu, ps1, 2);
        l0 = l0 * a0 + ps0;
        l1 = l1 * a1 + ps1;

        #pragma unroll
        for (int nt = 0; nt < 16; nt++) {
            o[nt][0] *= a0; o[nt][1] *= a0;
            o[nt][2] *= a1; o[nt][3] *= a1;
        }

        // ---- pack P fragments (hi/lo split, C-frag -> A-frag remap) ----
        uint32_t pah[2][4], pal[2][4];
        #pragma unroll
        for (int j = 0; j < 2; j++) {
            #pragma unroll
            for (int half = 0; half < 2; half++) {
                float v0 = sc[2*j + half][0], v1 = sc[2*j + half][1];
                float v2 = sc[2*j + half][2], v3 = sc[2*j + half][3];
                float h0 = __bfloat162float(__float2bfloat16_rn(v0));
                float h1 = __bfloat162float(__float2bfloat16_rn(v1));
                float h2 = __bfloat162float(__float2bfloat16_rn(v2));
                float h3 = __bfloat162float(__float2bfloat16_rn(v3));
                pah[j][2*half + 0] = packbf2(h0, h1);
                pah[j][2*half + 1] = packbf2(h2, h3);
                pal[j][2*half + 0] = packbf2(v0 - h0, v1 - h1);
                pal[j][2*half + 1] = packbf2(v2 - h2, v3 - h3);
            }
        }

        // ---- O += P V ----
        #pragma unroll
        for (int j = 0; j < 2; j++) {
            #pragma unroll
            for (int nt2 = 0; nt2 < 8; nt2++) {
                int row = 16 * j + vrow;
                int col = 16 * nt2 + vsel;
                uint32_t r0, r1, r2, r3, u0, u1, u2, u3;
                ldsm4t(r0, r1, r2, r3, sptr(&sVh[row * KLD + col]));
                ldsm4t(u0, u1, u2, u3, sptr(&sVl[row * KLD + col]));
                mma_bf16(o[2*nt2],   pah[j], r0, r1);
                mma_bf16(o[2*nt2+1], pah[j], r2, r3);
                mma_bf16(o[2*nt2],   pah[j], u0, u1);
                mma_bf16(o[2*nt2+1], pah[j], u2, u3);
                mma_bf16(o[2*nt2],   pal[j], r0, r1);
                mma_bf16(o[2*nt2+1], pal[j], r2, r3);
            }
        }
        __syncthreads();
    }

    // ---- epilogue: write ctx split bf16 ----
    float i0 = 1.0f / l0, i1 = 1.0f / l1;
    size_t base0 = (qrow0 + g) * EMBED + h * HDIM + 2 * t;
    size_t base1 = (qrow0 + g + 8) * EMBED + h * HDIM + 2 * t;
    #pragma unroll
    for (int nt = 0; nt < 16; nt++) {
        split_store2(o[nt][0] * i0, o[nt][1] * i0, &ctxh[base0 + 8 * nt], &ctxl[base0 + 8 * nt]);
        split_store2(o[nt][2] * i1, o[nt][3] * i1, &ctxh[base1 + 8 * nt], &ctxl[base1 + 8 * nt]);
    }
}

// ============================================================
// launcher
// ============================================================
extern "C" void kernel_launch(void* const* d_in, const int* in_sizes, int n_in,
                              void* d_out, int out_size)
{
    const float* query = (const float*)d_in[0];
    const float* key   = (const float*)d_in[1];
    const float* value = (const float*)d_in[2];
    const float* mask  = (const float*)d_in[3];
    const float* Wq    = (const float*)d_in[4];
    const float* Wk    = (const float*)d_in[5];
    const float* Wv    = (const float*)d_in[6];
    const float* Wo    = (const float*)d_in[7];
    float* out = (float*)d_out;

    bf16 *inh, *inl, *wh, *wl, *qh, *ql, *kh, *kl, *vh, *vl, *ctxh, *ctxl;
    cudaGetSymbolAddress((void**)&inh, g_inh);
    cudaGetSymbolAddress((void**)&inl, g_inl);
    cudaGetSymbolAddress((void**)&wh,  g_wh);
    cudaGetSymbolAddress((void**)&wl,  g_wl);
    cudaGetSymbolAddress((void**)&qh,  g_qh);
    cudaGetSymbolAddress((void**)&ql,  g_ql);
    cudaGetSymbolAddress((void**)&kh,  g_kh);
    cudaGetSymbolAddress((void**)&kl,  g_kl);
    cudaGetSymbolAddress((void**)&vh,  g_vh);
    cudaGetSymbolAddress((void**)&vl,  g_vl);
    cudaGetSymbolAddress((void**)&ctxh, g_ctxh);
    cudaGetSymbolAddress((void**)&ctxl, g_ctxl);

    cudaFuncSetAttribute(attn_mma, cudaFuncAttributeMaxDynamicSharedMemorySize, ATTN_SMEM);
    cudaFuncSetAttribute(gemm_sp<true>,  cudaFuncAttributeMaxDynamicSharedMemorySize, GEMM_SMEM);
    cudaFuncSetAttribute(gemm_sp<false>, cudaFuncAttributeMaxDynamicSharedMemorySize, GEMM_SMEM);

    dim3 blk(256);

    // ---- split passes ----
    {
        int n4;
        n4 = IN_STRIDE / 4;
        split_kernel<<<(n4 + 255) / 256, blk>>>(query, inh + 0 * (size_t)IN_STRIDE, inl + 0 * (size_t)IN_STRIDE, n4);
        split_kernel<<<(n4 + 255) / 256, blk>>>(key,   inh + 1 * (size_t)IN_STRIDE, inl + 1 * (size_t)IN_STRIDE, n4);
        split_kernel<<<(n4 + 255) / 256, blk>>>(value, inh + 2 * (size_t)IN_STRIDE, inl + 2 * (size_t)IN_STRIDE, n4);
        n4 = (EMBED * EMBED) / 4;
        split_kernel<<<(n4 + 255) / 256, blk>>>(Wq, wh + WQ_OFF, wl + WQ_OFF, n4);
        split_kernel<<<(n4 + 255) / 256, blk>>>(Wo, wh + WO_OFF, wl + WO_OFF, n4);
        n4 = (EMBED * KVDIM) / 4;
        split_kernel<<<(n4 + 255) / 256, blk>>>(Wk, wh + WK_OFF, wl + WK_OFF, n4);
        split_kernel<<<(n4 + 255) / 256, blk>>>(Wv, wh + WV_OFF, wl + WV_OFF, n4);
    }

    // ---- projections ----
    gemm_sp<true><<<dim3(EMBED / 128, MROWS / 128), blk, GEMM_SMEM>>>(
        MROWS, EMBED, EMBED,
        inh + 0 * (size_t)IN_STRIDE, inl + 0 * (size_t)IN_STRIDE,
        wh + WQ_OFF, wl + WQ_OFF, nullptr, qh, ql);
    gemm_sp<true><<<dim3(KVDIM / 128, MROWS / 128), blk, GEMM_SMEM>>>(
        MROWS, KVDIM, EMBED,
        inh + 1 * (size_t)IN_STRIDE, inl + 1 * (size_t)IN_STRIDE,
        wh + WK_OFF, wl + WK_OFF, nullptr, kh, kl);
    gemm_sp<true><<<dim3(KVDIM / 128, MROWS / 128), blk, GEMM_SMEM>>>(
        MROWS, KVDIM, EMBED,
        inh + 2 * (size_t)IN_STRIDE, inl + 2 * (size_t)IN_STRIDE,
        wh + WV_OFF, wl + WV_OFF, nullptr, vh, vl);

    // ---- fused attention (4 warps/CTA, 2 CTAs/SM) ----
    attn_mma<<<dim3(SS / 64, NHEAD, BB), dim3(128), ATTN_SMEM>>>(
        qh, ql, kh, kl, vh, vl, mask, ctxh, ctxl);

    // ---- output projection (fp32 out) ----
    gemm_sp<false><<<dim3(EMBED / 128, MROWS / 128), blk, GEMM_SMEM>>>(
        MROWS, EMBED, EMBED, ctxh, ctxl, wh + WO_OFF, wl + WO_OFF, out, nullptr, nullptr);
}